// round 11
// baseline (speedup 1.0000x reference)
#include <cuda_runtime.h>
#include <math.h>

// Chamfer distance, B=4, N=M=8192, 3D.
// d_out (float32): dist1[B*N] | dist2[B*M] | idx1[B*N] | idx2[B*M]
// R3-proven structure (best: 133.4us), with the distance switched to packed
// FMA: d = fma(dx,dx, fma(dy,dy, dz*dz)). 6 packed ops/pair instead of 8
// (-25% on the binding fma pipe). Distances differ from XLA by <~2ulp —
// far inside the 1e-3 tolerance; argmin flip probability ~0.1 expected
// across all outputs (fixed seed, one-shot).
//  - candidates staged NEGATED in smem; LDS.128 as ulonglong2 operands
//  - argmin recovered in-loop from the SAME registers that produced the min
//  - 2 segment-threads per query; exact lexicographic (d, idx) combine

#define QPB 128            // 64 queries x 2 segments
#define NQ_BLK 64
#define NSEG 2
#define CH 1024            // candidates staged per chunk
#define SEG 512            // candidates per segment per chunk

typedef unsigned long long u64;

__device__ __forceinline__ void unpack2(float& lo, float& hi, u64 v) {
    asm("mov.b64 {%0, %1}, %2;" : "=f"(lo), "=f"(hi) : "l"(v));
}
__device__ __forceinline__ u64 pack2(float lo, float hi) {
    u64 r;
    asm("mov.b64 %0, {%1, %2};" : "=l"(r) : "f"(lo), "f"(hi));
    return r;
}
__device__ __forceinline__ u64 add2(u64 a, u64 b) {
    u64 r;
    asm("add.rn.f32x2 %0, %1, %2;" : "=l"(r) : "l"(a), "l"(b));
    return r;
}
__device__ __forceinline__ u64 mul2(u64 a, u64 b) {
    u64 r;
    asm("mul.rn.f32x2 %0, %1, %2;" : "=l"(r) : "l"(a), "l"(b));
    return r;
}
__device__ __forceinline__ u64 fma2(u64 a, u64 b, u64 c) {
    u64 r;
    asm("fma.rn.f32x2 %0, %1, %2, %3;" : "=l"(r) : "l"(a), "l"(b), "l"(c));
    return r;
}
__device__ __forceinline__ float negf(float x) {
    return __int_as_float(__float_as_int(x) ^ 0x80000000);
}

__global__ __launch_bounds__(QPB) void chamfer_kernel(
    const float* __restrict__ xyz1,
    const float* __restrict__ xyz2,
    float* __restrict__ out,
    int N, int M, int B)
{
    __shared__ __align__(16) float smem_f[3 * CH];   // negated SoA: x | y | z
    __shared__ float rbest[QPB];
    __shared__ int   rbi[QPB];

    float* sx = smem_f;
    float* sy = smem_f + CH;
    float* sz = smem_f + 2 * CH;

    const int dir = blockIdx.z;   // 0: xyz1->xyz2, 1: xyz2->xyz1
    const int b   = blockIdx.y;

    const float* q; const float* c;
    float* outd; float* outi;
    int Nq, Nc;
    if (dir == 0) {
        q = xyz1; c = xyz2; Nq = N; Nc = M;
        outd = out;
        outi = out + (size_t)B * N + (size_t)B * M;
    } else {
        q = xyz2; c = xyz1; Nq = M; Nc = N;
        outd = out + (size_t)B * N;
        outi = out + (size_t)B * N + (size_t)B * M + (size_t)B * N;
    }

    const int tid = threadIdx.x;
    const int ql  = tid & (NQ_BLK - 1);   // query lane
    const int seg = tid >> 6;             // 0 or 1: candidate segment
    const int qi  = blockIdx.x * NQ_BLK + ql;

    const float* qb = q + ((size_t)b * Nq + qi) * 3;
    const float* cb = c + (size_t)b * Nc * 3;

    const float px = qb[0];
    const float py = qb[1];
    const float pz = qb[2];
    const u64 pxx = pack2(px, px);
    const u64 pyy = pack2(py, py);
    const u64 pzz = pack2(pz, pz);

    // Segment views of the staged chunk (64-bit lanes, LDS.128 pairs).
    const ulonglong2* sxv = (const ulonglong2*)(sx + seg * SEG);
    const ulonglong2* syv = (const ulonglong2*)(sy + seg * SEG);
    const ulonglong2* szv = (const ulonglong2*)(sz + seg * SEG);

    float best = INFINITY;
    int   bi   = 0;

    for (int base = 0; base < Nc; base += CH) {
        __syncthreads();
        // Stage CH candidates, sign-flipped (XOR, exact negate).
        for (int t = tid; t < CH; t += QPB) {
            const float* p = cb + (size_t)(base + t) * 3;
            sx[t] = negf(p[0]);
            sy[t] = negf(p[1]);
            sz[t] = negf(p[2]);
        }
        __syncthreads();

        const int segbase = base + seg * SEG;

        #pragma unroll 4
        for (int g = 0; g < SEG / 8; ++g) {
            const ulonglong2 X0 = sxv[2 * g], X1 = sxv[2 * g + 1];
            const ulonglong2 Y0 = syv[2 * g], Y1 = syv[2 * g + 1];
            const ulonglong2 Z0 = szv[2 * g], Z1 = szv[2 * g + 1];

            // dx = px + (-cx): identical rounding to px - cx.
            u64 dx0 = add2(pxx, X0.x), dx1 = add2(pxx, X0.y);
            u64 dx2 = add2(pxx, X1.x), dx3 = add2(pxx, X1.y);
            u64 dy0 = add2(pyy, Y0.x), dy1 = add2(pyy, Y0.y);
            u64 dy2 = add2(pyy, Y1.x), dy3 = add2(pyy, Y1.y);
            u64 dz0 = add2(pzz, Z0.x), dz1 = add2(pzz, Z0.y);
            u64 dz2 = add2(pzz, Z1.x), dz3 = add2(pzz, Z1.y);

            // d = fma(dx,dx, fma(dy,dy, dz*dz)) per lane (FMA-contracted).
            u64 d01 = fma2(dx0, dx0, fma2(dy0, dy0, mul2(dz0, dz0)));
            u64 d23 = fma2(dx1, dx1, fma2(dy1, dy1, mul2(dz1, dz1)));
            u64 d45 = fma2(dx2, dx2, fma2(dy2, dy2, mul2(dz2, dz2)));
            u64 d67 = fma2(dx3, dx3, fma2(dy3, dy3, mul2(dz3, dz3)));

            float d0, d1, d2, d3, d4, d5, d6, d7;
            unpack2(d0, d1, d01);
            unpack2(d2, d3, d23);
            unpack2(d4, d5, d45);
            unpack2(d6, d7, d67);

            const float m = fminf(fminf(fminf(d0, d1), fminf(d2, d3)),
                                  fminf(fminf(d4, d5), fminf(d6, d7)));

            if (m < best) {   // strict <: earlier groups win ties within segment
                best = m;
                const int jb = segbase + g * 8;
                // First-occurrence within group, from the SAME registers that
                // produced m: descending scan, lowest matching k wins.
                int s = jb + 7;
                if (d6 == m) s = jb + 6;
                if (d5 == m) s = jb + 5;
                if (d4 == m) s = jb + 4;
                if (d3 == m) s = jb + 3;
                if (d2 == m) s = jb + 2;
                if (d1 == m) s = jb + 1;
                if (d0 == m) s = jb;
                bi = s;
            }
        }
    }

    rbest[tid] = best;
    rbi[tid]   = bi;
    __syncthreads();

    // Combine 2 segments per query: lexicographic (d, idx) min == first occurrence.
    if (tid < NQ_BLK) {
        float bd  = rbest[tid];
        int   bix = rbi[tid];
        const float od = rbest[tid + NQ_BLK];
        const int   oi = rbi[tid + NQ_BLK];
        if (od < bd || (od == bd && oi < bix)) { bd = od; bix = oi; }
        outd[(size_t)b * Nq + qi] = bd;
        outi[(size_t)b * Nq + qi] = (float)bix;   // <= 8191, exact in fp32
    }
}

extern "C" void kernel_launch(void* const* d_in, const int* in_sizes, int n_in,
                              void* d_out, int out_size)
{
    const float* xyz1 = (const float*)d_in[0];  // [4, 8192, 3]
    const float* xyz2 = (const float*)d_in[1];  // [4, 8192, 3]
    float* out = (float*)d_out;

    const int B = 4;
    const int N = in_sizes[0] / (B * 3);  // 8192
    const int M = in_sizes[1] / (B * 3);  // 8192

    dim3 block(QPB, 1, 1);
    dim3 grid(N / NQ_BLK, B, 2);   // 1024 blocks x 128 threads
    chamfer_kernel<<<grid, block>>>(xyz1, xyz2, out, N, M, B);
}

// round 14
// speedup vs baseline: 1.0653x; 1.0653x over previous
#include <cuda_runtime.h>
#include <math.h>

// Chamfer distance, B=4, N=M=8192, 3D.
// d_out (float32): dist1[B*N] | dist2[B*M] | idx1[B*N] | idx2[B*M]
// Combination of all session-proven wins:
//  - packed f32x2 FMA body (R11: fewest fp ops, no argmin flips)
//  - 2048-block / 4-segment topology (R5: best measured issue%)
//  - BRANCHLESS hot loop (FSETP+SEL tracking, no BSSY/BSYNC); winning group
//    recomputed once per improving chunk from the SAME smem data with the
//    SAME packed helpers -> bit-exact index recovery (safe, unlike R4's
//    scalar/GMEM cross-path which was proven non-bit-identical)
//  - exact first-occurrence ties: strict < across groups/chunks, descending
//    in-group scan, lexicographic (d, idx) combine across segments

#define QPB 128            // 32 queries x 4 segments
#define NQ_BLK 32
#define NSEG 4
#define CH 1024            // candidates staged per chunk
#define SEG 256            // candidates per segment per chunk
#define NGRP (SEG / 8)     // 32 groups per chunk per segment

typedef unsigned long long u64;

__device__ __forceinline__ void unpack2(float& lo, float& hi, u64 v) {
    asm("mov.b64 {%0, %1}, %2;" : "=f"(lo), "=f"(hi) : "l"(v));
}
__device__ __forceinline__ u64 pack2(float lo, float hi) {
    u64 r;
    asm("mov.b64 %0, {%1, %2};" : "=l"(r) : "f"(lo), "f"(hi));
    return r;
}
__device__ __forceinline__ u64 add2(u64 a, u64 b) {
    u64 r;
    asm("add.rn.f32x2 %0, %1, %2;" : "=l"(r) : "l"(a), "l"(b));
    return r;
}
__device__ __forceinline__ u64 mul2(u64 a, u64 b) {
    u64 r;
    asm("mul.rn.f32x2 %0, %1, %2;" : "=l"(r) : "l"(a), "l"(b));
    return r;
}
__device__ __forceinline__ u64 fma2(u64 a, u64 b, u64 c) {
    u64 r;
    asm("fma.rn.f32x2 %0, %1, %2, %3;" : "=l"(r) : "l"(a), "l"(b), "l"(c));
    return r;
}
__device__ __forceinline__ float negf(float x) {
    return __int_as_float(__float_as_int(x) ^ 0x80000000);
}

// One 8-candidate group: distances via identical packed op sequence.
// Used by BOTH the hot loop and the recovery path -> bit-exact agreement.
__device__ __forceinline__ void group_dists(
    const ulonglong2* sxv, const ulonglong2* syv, const ulonglong2* szv,
    int g, u64 pxx, u64 pyy, u64 pzz,
    float& d0, float& d1, float& d2, float& d3,
    float& d4, float& d5, float& d6, float& d7)
{
    const ulonglong2 X0 = sxv[2 * g], X1 = sxv[2 * g + 1];
    const ulonglong2 Y0 = syv[2 * g], Y1 = syv[2 * g + 1];
    const ulonglong2 Z0 = szv[2 * g], Z1 = szv[2 * g + 1];
    u64 dx0 = add2(pxx, X0.x), dx1 = add2(pxx, X0.y);
    u64 dx2 = add2(pxx, X1.x), dx3 = add2(pxx, X1.y);
    u64 dy0 = add2(pyy, Y0.x), dy1 = add2(pyy, Y0.y);
    u64 dy2 = add2(pyy, Y1.x), dy3 = add2(pyy, Y1.y);
    u64 dz0 = add2(pzz, Z0.x), dz1 = add2(pzz, Z0.y);
    u64 dz2 = add2(pzz, Z1.x), dz3 = add2(pzz, Z1.y);
    u64 d01 = fma2(dx0, dx0, fma2(dy0, dy0, mul2(dz0, dz0)));
    u64 d23 = fma2(dx1, dx1, fma2(dy1, dy1, mul2(dz1, dz1)));
    u64 d45 = fma2(dx2, dx2, fma2(dy2, dy2, mul2(dz2, dz2)));
    u64 d67 = fma2(dx3, dx3, fma2(dy3, dy3, mul2(dz3, dz3)));
    unpack2(d0, d1, d01);
    unpack2(d2, d3, d23);
    unpack2(d4, d5, d45);
    unpack2(d6, d7, d67);
}

__global__ __launch_bounds__(QPB) void chamfer_kernel(
    const float* __restrict__ xyz1,
    const float* __restrict__ xyz2,
    float* __restrict__ out,
    int N, int M, int B)
{
    __shared__ __align__(16) float smem_f[3 * CH];   // negated SoA: x | y | z
    __shared__ float rbest[NSEG * NQ_BLK];
    __shared__ int   rbi[NSEG * NQ_BLK];

    float* sx = smem_f;
    float* sy = smem_f + CH;
    float* sz = smem_f + 2 * CH;

    const int dir = blockIdx.z;   // 0: xyz1->xyz2, 1: xyz2->xyz1
    const int b   = blockIdx.y;

    const float* q; const float* c;
    float* outd; float* outi;
    int Nq, Nc;
    if (dir == 0) {
        q = xyz1; c = xyz2; Nq = N; Nc = M;
        outd = out;
        outi = out + (size_t)B * N + (size_t)B * M;
    } else {
        q = xyz2; c = xyz1; Nq = M; Nc = N;
        outd = out + (size_t)B * N;
        outi = out + (size_t)B * N + (size_t)B * M + (size_t)B * N;
    }

    const int tid  = threadIdx.x;
    const int slot = tid & (NQ_BLK - 1);  // 0..31: query lane
    const int seg  = tid >> 5;            // 0..3: candidate segment
    const int qi   = blockIdx.x * NQ_BLK + slot;

    const float* qb = q + ((size_t)b * Nq + qi) * 3;
    const float* cb = c + (size_t)b * Nc * 3;

    const u64 pxx = pack2(qb[0], qb[0]);
    const u64 pyy = pack2(qb[1], qb[1]);
    const u64 pzz = pack2(qb[2], qb[2]);

    // Segment views of the staged chunk (64-bit lanes, LDS.128 pairs).
    const ulonglong2* sxv = (const ulonglong2*)(sx + seg * SEG);
    const ulonglong2* syv = (const ulonglong2*)(sy + seg * SEG);
    const ulonglong2* szv = (const ulonglong2*)(sz + seg * SEG);

    float best = INFINITY;
    int   bi   = 0;

    for (int base = 0; base < Nc; base += CH) {
        __syncthreads();   // protects smem from previous chunk's readers
        for (int t = tid; t < CH; t += QPB) {
            const float* p = cb + (size_t)(base + t) * 3;
            sx[t] = negf(p[0]);
            sy[t] = negf(p[1]);
            sz[t] = negf(p[2]);
        }
        __syncthreads();

        const int segbase = base + seg * SEG;

        // Branchless chunk-local tracking.
        float cbest = INFINITY;
        int   cg    = 0;

        #pragma unroll 8
        for (int g = 0; g < NGRP; ++g) {
            float d0, d1, d2, d3, d4, d5, d6, d7;
            group_dists(sxv, syv, szv, g, pxx, pyy, pzz,
                        d0, d1, d2, d3, d4, d5, d6, d7);
            const float m = fminf(fminf(fminf(d0, d1), fminf(d2, d3)),
                                  fminf(fminf(d4, d5), fminf(d6, d7)));
            const bool imp = m < cbest;   // strict <: earliest group wins ties
            cbest = imp ? m : cbest;
            cg    = imp ? g : cg;
        }

        // Rare (<= once per chunk): recover in-group index by recomputing the
        // winning group from the SAME smem data with the SAME packed ops
        // (bit-exact). Runs before the next chunk's staging sync, so the
        // data is still resident.
        if (cbest < best) {
            best = cbest;
            float d0, d1, d2, d3, d4, d5, d6, d7;
            group_dists(sxv, syv, szv, cg, pxx, pyy, pzz,
                        d0, d1, d2, d3, d4, d5, d6, d7);
            const int jb = segbase + cg * 8;
            int s = jb + 7;   // descending scan: lowest matching k wins
            if (d6 == cbest) s = jb + 6;
            if (d5 == cbest) s = jb + 5;
            if (d4 == cbest) s = jb + 4;
            if (d3 == cbest) s = jb + 3;
            if (d2 == cbest) s = jb + 2;
            if (d1 == cbest) s = jb + 1;
            if (d0 == cbest) s = jb;
            bi = s;
        }
    }

    rbest[seg * NQ_BLK + slot] = best;
    rbi[seg * NQ_BLK + slot]   = bi;
    __syncthreads();

    // Combine 4 segments per query: lexicographic (d, idx) min == first occurrence.
    if (tid < NQ_BLK) {
        float bd  = rbest[tid];
        int   bix = rbi[tid];
        #pragma unroll
        for (int s = 1; s < NSEG; ++s) {
            const float od = rbest[s * NQ_BLK + tid];
            const int   oi = rbi[s * NQ_BLK + tid];
            if (od < bd || (od == bd && oi < bix)) { bd = od; bix = oi; }
        }
        const int qo = blockIdx.x * NQ_BLK + tid;
        outd[(size_t)b * Nq + qo] = bd;
        outi[(size_t)b * Nq + qo] = (float)bix;   // <= 8191, exact in fp32
    }
}

extern "C" void kernel_launch(void* const* d_in, const int* in_sizes, int n_in,
                              void* d_out, int out_size)
{
    const float* xyz1 = (const float*)d_in[0];  // [4, 8192, 3]
    const float* xyz2 = (const float*)d_in[1];  // [4, 8192, 3]
    float* out = (float*)d_out;

    const int B = 4;
    const int N = in_sizes[0] / (B * 3);  // 8192
    const int M = in_sizes[1] / (B * 3);  // 8192

    dim3 block(QPB, 1, 1);
    dim3 grid(N / NQ_BLK, B, 2);   // 2048 blocks x 128 threads
    chamfer_kernel<<<grid, block>>>(xyz1, xyz2, out, N, M, B);
}

// round 15
// speedup vs baseline: 1.1062x; 1.0384x over previous
#include <cuda_runtime.h>
#include <math.h>

// Chamfer distance, B=4, N=M=8192, 3D.
// d_out (float32): dist1[B*N] | dist2[B*M] | idx1[B*N] | idx2[B*M]
// R14 (best: 132.4us) + manual software pipeline: double-buffered group
// operands force cross-group ILP that ptxas refused to create (regs=34
// proved the unroll was collapsed). LDS for group g+1 issues while group g
// computes -> 29-cycle LDS latency covered, two fp chains in flight.
//  - packed f32x2 FMA body (proven: no argmin flips, rel_err 4.5e-8)
//  - branchless chunk tracking; winning group recomputed from the SAME smem
//    with the SAME packed helpers (bit-exact index recovery)
//  - exact first-occurrence ties: strict < across groups/chunks, descending
//    in-group scan, lexicographic (d, idx) combine across segments

#define QPB 128            // 32 queries x 4 segments
#define NQ_BLK 32
#define NSEG 4
#define CH 1024            // candidates staged per chunk
#define SEG 256            // candidates per segment per chunk
#define NGRP (SEG / 8)     // 32 groups per chunk per segment

typedef unsigned long long u64;

__device__ __forceinline__ void unpack2(float& lo, float& hi, u64 v) {
    asm("mov.b64 {%0, %1}, %2;" : "=f"(lo), "=f"(hi) : "l"(v));
}
__device__ __forceinline__ u64 pack2(float lo, float hi) {
    u64 r;
    asm("mov.b64 %0, {%1, %2};" : "=l"(r) : "f"(lo), "f"(hi));
    return r;
}
__device__ __forceinline__ u64 add2(u64 a, u64 b) {
    u64 r;
    asm("add.rn.f32x2 %0, %1, %2;" : "=l"(r) : "l"(a), "l"(b));
    return r;
}
__device__ __forceinline__ u64 mul2(u64 a, u64 b) {
    u64 r;
    asm("mul.rn.f32x2 %0, %1, %2;" : "=l"(r) : "l"(a), "l"(b));
    return r;
}
__device__ __forceinline__ u64 fma2(u64 a, u64 b, u64 c) {
    u64 r;
    asm("fma.rn.f32x2 %0, %1, %2, %3;" : "=l"(r) : "l"(a), "l"(b), "l"(c));
    return r;
}
__device__ __forceinline__ float negf(float x) {
    return __int_as_float(__float_as_int(x) ^ 0x80000000);
}

// Distances for one 8-candidate group from its 6 preloaded 16B vectors.
// IDENTICAL op sequence everywhere it is used -> bit-exact agreement
// between the hot loop and the recovery path.
__device__ __forceinline__ void group_dists_v(
    ulonglong2 X0, ulonglong2 X1, ulonglong2 Y0, ulonglong2 Y1,
    ulonglong2 Z0, ulonglong2 Z1,
    u64 pxx, u64 pyy, u64 pzz,
    float& d0, float& d1, float& d2, float& d3,
    float& d4, float& d5, float& d6, float& d7)
{
    u64 dx0 = add2(pxx, X0.x), dx1 = add2(pxx, X0.y);
    u64 dx2 = add2(pxx, X1.x), dx3 = add2(pxx, X1.y);
    u64 dy0 = add2(pyy, Y0.x), dy1 = add2(pyy, Y0.y);
    u64 dy2 = add2(pyy, Y1.x), dy3 = add2(pyy, Y1.y);
    u64 dz0 = add2(pzz, Z0.x), dz1 = add2(pzz, Z0.y);
    u64 dz2 = add2(pzz, Z1.x), dz3 = add2(pzz, Z1.y);
    u64 d01 = fma2(dx0, dx0, fma2(dy0, dy0, mul2(dz0, dz0)));
    u64 d23 = fma2(dx1, dx1, fma2(dy1, dy1, mul2(dz1, dz1)));
    u64 d45 = fma2(dx2, dx2, fma2(dy2, dy2, mul2(dz2, dz2)));
    u64 d67 = fma2(dx3, dx3, fma2(dy3, dy3, mul2(dz3, dz3)));
    unpack2(d0, d1, d01);
    unpack2(d2, d3, d23);
    unpack2(d4, d5, d45);
    unpack2(d6, d7, d67);
}

__global__ __launch_bounds__(QPB) void chamfer_kernel(
    const float* __restrict__ xyz1,
    const float* __restrict__ xyz2,
    float* __restrict__ out,
    int N, int M, int B)
{
    __shared__ __align__(16) float smem_f[3 * CH];   // negated SoA: x | y | z
    __shared__ float rbest[NSEG * NQ_BLK];
    __shared__ int   rbi[NSEG * NQ_BLK];

    float* sx = smem_f;
    float* sy = smem_f + CH;
    float* sz = smem_f + 2 * CH;

    const int dir = blockIdx.z;   // 0: xyz1->xyz2, 1: xyz2->xyz1
    const int b   = blockIdx.y;

    const float* q; const float* c;
    float* outd; float* outi;
    int Nq, Nc;
    if (dir == 0) {
        q = xyz1; c = xyz2; Nq = N; Nc = M;
        outd = out;
        outi = out + (size_t)B * N + (size_t)B * M;
    } else {
        q = xyz2; c = xyz1; Nq = M; Nc = N;
        outd = out + (size_t)B * N;
        outi = out + (size_t)B * N + (size_t)B * M + (size_t)B * N;
    }

    const int tid  = threadIdx.x;
    const int slot = tid & (NQ_BLK - 1);  // 0..31: query lane
    const int seg  = tid >> 5;            // 0..3: candidate segment
    const int qi   = blockIdx.x * NQ_BLK + slot;

    const float* qb = q + ((size_t)b * Nq + qi) * 3;
    const float* cb = c + (size_t)b * Nc * 3;

    const u64 pxx = pack2(qb[0], qb[0]);
    const u64 pyy = pack2(qb[1], qb[1]);
    const u64 pzz = pack2(qb[2], qb[2]);

    // Segment views of the staged chunk (64-bit lanes, LDS.128 pairs).
    const ulonglong2* sxv = (const ulonglong2*)(sx + seg * SEG);
    const ulonglong2* syv = (const ulonglong2*)(sy + seg * SEG);
    const ulonglong2* szv = (const ulonglong2*)(sz + seg * SEG);

    float best = INFINITY;
    int   bi   = 0;

    for (int base = 0; base < Nc; base += CH) {
        __syncthreads();   // protect smem from previous chunk's readers
        for (int t = tid; t < CH; t += QPB) {
            const float* p = cb + (size_t)(base + t) * 3;
            sx[t] = negf(p[0]);
            sy[t] = negf(p[1]);
            sz[t] = negf(p[2]);
        }
        __syncthreads();

        const int segbase = base + seg * SEG;

        // Branchless chunk-local tracking.
        float cbest = INFINITY;
        int   cg    = 0;

        // ---- software pipeline: preload group 0 ----
        ulonglong2 aX0 = sxv[0], aX1 = sxv[1];
        ulonglong2 aY0 = syv[0], aY1 = syv[1];
        ulonglong2 aZ0 = szv[0], aZ1 = szv[1];

        #pragma unroll 4
        for (int g = 0; g < NGRP; ++g) {
            // Prefetch group g+1 into the second buffer while computing g.
            ulonglong2 nX0, nX1, nY0, nY1, nZ0, nZ1;
            if (g + 1 < NGRP) {
                nX0 = sxv[2 * g + 2]; nX1 = sxv[2 * g + 3];
                nY0 = syv[2 * g + 2]; nY1 = syv[2 * g + 3];
                nZ0 = szv[2 * g + 2]; nZ1 = szv[2 * g + 3];
            }

            float d0, d1, d2, d3, d4, d5, d6, d7;
            group_dists_v(aX0, aX1, aY0, aY1, aZ0, aZ1,
                          pxx, pyy, pzz,
                          d0, d1, d2, d3, d4, d5, d6, d7);
            const float m = fminf(fminf(fminf(d0, d1), fminf(d2, d3)),
                                  fminf(fminf(d4, d5), fminf(d6, d7)));
            const bool imp = m < cbest;   // strict <: earliest group wins ties
            cbest = imp ? m : cbest;
            cg    = imp ? g : cg;

            aX0 = nX0; aX1 = nX1;
            aY0 = nY0; aY1 = nY1;
            aZ0 = nZ0; aZ1 = nZ1;
        }

        // Rare (<= once per chunk): recover in-group index by recomputing the
        // winning group from the SAME smem data with the SAME packed ops
        // (bit-exact). Runs before the next chunk's staging sync.
        if (cbest < best) {
            best = cbest;
            const ulonglong2 X0 = sxv[2 * cg], X1 = sxv[2 * cg + 1];
            const ulonglong2 Y0 = syv[2 * cg], Y1 = syv[2 * cg + 1];
            const ulonglong2 Z0 = szv[2 * cg], Z1 = szv[2 * cg + 1];
            float d0, d1, d2, d3, d4, d5, d6, d7;
            group_dists_v(X0, X1, Y0, Y1, Z0, Z1,
                          pxx, pyy, pzz,
                          d0, d1, d2, d3, d4, d5, d6, d7);
            const int jb = segbase + cg * 8;
            int s = jb + 7;   // descending scan: lowest matching k wins
            if (d6 == cbest) s = jb + 6;
            if (d5 == cbest) s = jb + 5;
            if (d4 == cbest) s = jb + 4;
            if (d3 == cbest) s = jb + 3;
            if (d2 == cbest) s = jb + 2;
            if (d1 == cbest) s = jb + 1;
            if (d0 == cbest) s = jb;
            bi = s;
        }
    }

    rbest[seg * NQ_BLK + slot] = best;
    rbi[seg * NQ_BLK + slot]   = bi;
    __syncthreads();

    // Combine 4 segments per query: lexicographic (d, idx) min == first occurrence.
    if (tid < NQ_BLK) {
        float bd  = rbest[tid];
        int   bix = rbi[tid];
        #pragma unroll
        for (int s = 1; s < NSEG; ++s) {
            const float od = rbest[s * NQ_BLK + tid];
            const int   oi = rbi[s * NQ_BLK + tid];
            if (od < bd || (od == bd && oi < bix)) { bd = od; bix = oi; }
        }
        const int qo = blockIdx.x * NQ_BLK + tid;
        outd[(size_t)b * Nq + qo] = bd;
        outi[(size_t)b * Nq + qo] = (float)bix;   // <= 8191, exact in fp32
    }
}

extern "C" void kernel_launch(void* const* d_in, const int* in_sizes, int n_in,
                              void* d_out, int out_size)
{
    const float* xyz1 = (const float*)d_in[0];  // [4, 8192, 3]
    const float* xyz2 = (const float*)d_in[1];  // [4, 8192, 3]
    float* out = (float*)d_out;

    const int B = 4;
    const int N = in_sizes[0] / (B * 3);  // 8192
    const int M = in_sizes[1] / (B * 3);  // 8192

    dim3 block(QPB, 1, 1);
    dim3 grid(N / NQ_BLK, B, 2);   // 2048 blocks x 128 threads
    chamfer_kernel<<<grid, block>>>(xyz1, xyz2, out, N, M, B);
}

// round 16
// speedup vs baseline: 1.1265x; 1.0184x over previous
#include <cuda_runtime.h>
#include <math.h>

// Chamfer distance, B=4, N=M=8192, 3D.
// d_out (float32): dist1[B*N] | dist2[B*M] | idx1[B*N] | idx2[B*M]
// R15 (best: 127.5us) + 2 queries per thread: each pipelined group's 6
// LDS.128 now serve 16 pairs instead of 8, and the two queries' fp chains
// are independent (more ILP for the pipeline to exploit). Per-pair issue
// count drops ~5.75 -> ~4.75; LDS traffic halves.
//  - packed f32x2 FMA body (proven: no argmin flips, rel_err 4.5e-8)
//  - software-pipelined group operands (R15-proven)
//  - branchless chunk tracking; winning group recomputed from the SAME smem
//    with the SAME packed helpers (bit-exact index recovery)
//  - exact first-occurrence ties: strict < across groups/chunks, descending
//    in-group scan, lexicographic (d, idx) combine across segments

#define QPB 128            // 32 slots x 4 segments; 2 queries per thread
#define NQ_BLK 64          // queries per block
#define NSLOT 32
#define NSEG 4
#define CH 1024            // candidates staged per chunk
#define SEG 256            // candidates per segment per chunk
#define NGRP (SEG / 8)     // 32 groups per chunk per segment

typedef unsigned long long u64;

__device__ __forceinline__ void unpack2(float& lo, float& hi, u64 v) {
    asm("mov.b64 {%0, %1}, %2;" : "=f"(lo), "=f"(hi) : "l"(v));
}
__device__ __forceinline__ u64 pack2(float lo, float hi) {
    u64 r;
    asm("mov.b64 %0, {%1, %2};" : "=l"(r) : "f"(lo), "f"(hi));
    return r;
}
__device__ __forceinline__ u64 add2(u64 a, u64 b) {
    u64 r;
    asm("add.rn.f32x2 %0, %1, %2;" : "=l"(r) : "l"(a), "l"(b));
    return r;
}
__device__ __forceinline__ u64 mul2(u64 a, u64 b) {
    u64 r;
    asm("mul.rn.f32x2 %0, %1, %2;" : "=l"(r) : "l"(a), "l"(b));
    return r;
}
__device__ __forceinline__ u64 fma2(u64 a, u64 b, u64 c) {
    u64 r;
    asm("fma.rn.f32x2 %0, %1, %2, %3;" : "=l"(r) : "l"(a), "l"(b), "l"(c));
    return r;
}
__device__ __forceinline__ float negf(float x) {
    return __int_as_float(__float_as_int(x) ^ 0x80000000);
}

// Distances for one 8-candidate group from its 6 preloaded 16B vectors.
// IDENTICAL op sequence everywhere -> bit-exact agreement between the hot
// loop and the recovery path.
__device__ __forceinline__ void group_dists_v(
    ulonglong2 X0, ulonglong2 X1, ulonglong2 Y0, ulonglong2 Y1,
    ulonglong2 Z0, ulonglong2 Z1,
    u64 pxx, u64 pyy, u64 pzz,
    float& d0, float& d1, float& d2, float& d3,
    float& d4, float& d5, float& d6, float& d7)
{
    u64 dx0 = add2(pxx, X0.x), dx1 = add2(pxx, X0.y);
    u64 dx2 = add2(pxx, X1.x), dx3 = add2(pxx, X1.y);
    u64 dy0 = add2(pyy, Y0.x), dy1 = add2(pyy, Y0.y);
    u64 dy2 = add2(pyy, Y1.x), dy3 = add2(pyy, Y1.y);
    u64 dz0 = add2(pzz, Z0.x), dz1 = add2(pzz, Z0.y);
    u64 dz2 = add2(pzz, Z1.x), dz3 = add2(pzz, Z1.y);
    u64 d01 = fma2(dx0, dx0, fma2(dy0, dy0, mul2(dz0, dz0)));
    u64 d23 = fma2(dx1, dx1, fma2(dy1, dy1, mul2(dz1, dz1)));
    u64 d45 = fma2(dx2, dx2, fma2(dy2, dy2, mul2(dz2, dz2)));
    u64 d67 = fma2(dx3, dx3, fma2(dy3, dy3, mul2(dz3, dz3)));
    unpack2(d0, d1, d01);
    unpack2(d2, d3, d23);
    unpack2(d4, d5, d45);
    unpack2(d6, d7, d67);
}

// In-group first-occurrence argmin (descending scan on the min's registers).
__device__ __forceinline__ int group_argmin(
    float m, int jb,
    float d0, float d1, float d2, float d3,
    float d4, float d5, float d6, float d7)
{
    int s = jb + 7;
    if (d6 == m) s = jb + 6;
    if (d5 == m) s = jb + 5;
    if (d4 == m) s = jb + 4;
    if (d3 == m) s = jb + 3;
    if (d2 == m) s = jb + 2;
    if (d1 == m) s = jb + 1;
    if (d0 == m) s = jb;
    return s;
}

__global__ __launch_bounds__(QPB) void chamfer_kernel(
    const float* __restrict__ xyz1,
    const float* __restrict__ xyz2,
    float* __restrict__ out,
    int N, int M, int B)
{
    __shared__ __align__(16) float smem_f[3 * CH];   // negated SoA: x | y | z
    __shared__ float rbest[NSEG * NQ_BLK];
    __shared__ int   rbi[NSEG * NQ_BLK];

    float* sx = smem_f;
    float* sy = smem_f + CH;
    float* sz = smem_f + 2 * CH;

    const int dir = blockIdx.z;   // 0: xyz1->xyz2, 1: xyz2->xyz1
    const int b   = blockIdx.y;

    const float* q; const float* c;
    float* outd; float* outi;
    int Nq, Nc;
    if (dir == 0) {
        q = xyz1; c = xyz2; Nq = N; Nc = M;
        outd = out;
        outi = out + (size_t)B * N + (size_t)B * M;
    } else {
        q = xyz2; c = xyz1; Nq = M; Nc = N;
        outd = out + (size_t)B * N;
        outi = out + (size_t)B * N + (size_t)B * M + (size_t)B * N;
    }

    const int tid  = threadIdx.x;
    const int slot = tid & (NSLOT - 1);   // 0..31
    const int seg  = tid >> 5;            // 0..3: candidate segment
    const int qi0  = blockIdx.x * NQ_BLK + slot;   // query A
    const int qi1  = qi0 + NSLOT;                  // query B

    const float* qa = q + ((size_t)b * Nq + qi0) * 3;
    const float* qbp = q + ((size_t)b * Nq + qi1) * 3;
    const float* cb = c + (size_t)b * Nc * 3;

    const u64 paxx = pack2(qa[0], qa[0]);
    const u64 payy = pack2(qa[1], qa[1]);
    const u64 pazz = pack2(qa[2], qa[2]);
    const u64 pbxx = pack2(qbp[0], qbp[0]);
    const u64 pbyy = pack2(qbp[1], qbp[1]);
    const u64 pbzz = pack2(qbp[2], qbp[2]);

    // Segment views of the staged chunk (64-bit lanes, LDS.128 pairs).
    const ulonglong2* sxv = (const ulonglong2*)(sx + seg * SEG);
    const ulonglong2* syv = (const ulonglong2*)(sy + seg * SEG);
    const ulonglong2* szv = (const ulonglong2*)(sz + seg * SEG);

    float bestA = INFINITY, bestB = INFINITY;
    int   biA = 0, biB = 0;

    for (int base = 0; base < Nc; base += CH) {
        __syncthreads();   // protect smem from previous chunk's readers
        for (int t = tid; t < CH; t += QPB) {
            const float* p = cb + (size_t)(base + t) * 3;
            sx[t] = negf(p[0]);
            sy[t] = negf(p[1]);
            sz[t] = negf(p[2]);
        }
        __syncthreads();

        const int segbase = base + seg * SEG;

        // Branchless chunk-local tracking for both queries.
        float cbA = INFINITY, cbB = INFINITY;
        int   cgA = 0,        cgB = 0;

        // ---- software pipeline: preload group 0 ----
        ulonglong2 aX0 = sxv[0], aX1 = sxv[1];
        ulonglong2 aY0 = syv[0], aY1 = syv[1];
        ulonglong2 aZ0 = szv[0], aZ1 = szv[1];

        #pragma unroll 4
        for (int g = 0; g < NGRP; ++g) {
            // Prefetch group g+1 while computing g (both queries).
            ulonglong2 nX0, nX1, nY0, nY1, nZ0, nZ1;
            if (g + 1 < NGRP) {
                nX0 = sxv[2 * g + 2]; nX1 = sxv[2 * g + 3];
                nY0 = syv[2 * g + 2]; nY1 = syv[2 * g + 3];
                nZ0 = szv[2 * g + 2]; nZ1 = szv[2 * g + 3];
            }

            // ---- query A ----
            {
                float d0, d1, d2, d3, d4, d5, d6, d7;
                group_dists_v(aX0, aX1, aY0, aY1, aZ0, aZ1,
                              paxx, payy, pazz,
                              d0, d1, d2, d3, d4, d5, d6, d7);
                const float m = fminf(fminf(fminf(d0, d1), fminf(d2, d3)),
                                      fminf(fminf(d4, d5), fminf(d6, d7)));
                const bool imp = m < cbA;
                cbA = imp ? m : cbA;
                cgA = imp ? g : cgA;
            }
            // ---- query B ----
            {
                float d0, d1, d2, d3, d4, d5, d6, d7;
                group_dists_v(aX0, aX1, aY0, aY1, aZ0, aZ1,
                              pbxx, pbyy, pbzz,
                              d0, d1, d2, d3, d4, d5, d6, d7);
                const float m = fminf(fminf(fminf(d0, d1), fminf(d2, d3)),
                                      fminf(fminf(d4, d5), fminf(d6, d7)));
                const bool imp = m < cbB;
                cbB = imp ? m : cbB;
                cgB = imp ? g : cgB;
            }

            aX0 = nX0; aX1 = nX1;
            aY0 = nY0; aY1 = nY1;
            aZ0 = nZ0; aZ1 = nZ1;
        }

        // Rare: recover in-group indices by recomputing the winning group
        // from the SAME smem with the SAME packed ops (bit-exact). Runs
        // before the next chunk's staging sync, so data is still resident.
        if (cbA < bestA) {
            bestA = cbA;
            float d0, d1, d2, d3, d4, d5, d6, d7;
            group_dists_v(sxv[2 * cgA], sxv[2 * cgA + 1],
                          syv[2 * cgA], syv[2 * cgA + 1],
                          szv[2 * cgA], szv[2 * cgA + 1],
                          paxx, payy, pazz,
                          d0, d1, d2, d3, d4, d5, d6, d7);
            biA = group_argmin(cbA, segbase + cgA * 8,
                               d0, d1, d2, d3, d4, d5, d6, d7);
        }
        if (cbB < bestB) {
            bestB = cbB;
            float d0, d1, d2, d3, d4, d5, d6, d7;
            group_dists_v(sxv[2 * cgB], sxv[2 * cgB + 1],
                          syv[2 * cgB], syv[2 * cgB + 1],
                          szv[2 * cgB], szv[2 * cgB + 1],
                          pbxx, pbyy, pbzz,
                          d0, d1, d2, d3, d4, d5, d6, d7);
            biB = group_argmin(cbB, segbase + cgB * 8,
                               d0, d1, d2, d3, d4, d5, d6, d7);
        }
    }

    rbest[seg * NQ_BLK + slot]         = bestA;
    rbi[seg * NQ_BLK + slot]           = biA;
    rbest[seg * NQ_BLK + slot + NSLOT] = bestB;
    rbi[seg * NQ_BLK + slot + NSLOT]   = biB;
    __syncthreads();

    // Combine 4 segments per query: lexicographic (d, idx) min == first occurrence.
    if (tid < NQ_BLK) {
        float bd  = rbest[tid];
        int   bix = rbi[tid];
        #pragma unroll
        for (int s = 1; s < NSEG; ++s) {
            const float od = rbest[s * NQ_BLK + tid];
            const int   oi = rbi[s * NQ_BLK + tid];
            if (od < bd || (od == bd && oi < bix)) { bd = od; bix = oi; }
        }
        const int qo = blockIdx.x * NQ_BLK + tid;
        outd[(size_t)b * Nq + qo] = bd;
        outi[(size_t)b * Nq + qo] = (float)bix;   // <= 8191, exact in fp32
    }
}

extern "C" void kernel_launch(void* const* d_in, const int* in_sizes, int n_in,
                              void* d_out, int out_size)
{
    const float* xyz1 = (const float*)d_in[0];  // [4, 8192, 3]
    const float* xyz2 = (const float*)d_in[1];  // [4, 8192, 3]
    float* out = (float*)d_out;

    const int B = 4;
    const int N = in_sizes[0] / (B * 3);  // 8192
    const int M = in_sizes[1] / (B * 3);  // 8192

    dim3 block(QPB, 1, 1);
    dim3 grid(N / NQ_BLK, B, 2);   // 1024 blocks x 128 threads
    chamfer_kernel<<<grid, block>>>(xyz1, xyz2, out, N, M, B);
}